// round 1
// baseline (speedup 1.0000x reference)
#include <cuda_runtime.h>
#include <math.h>

#define NN 8192
#define FF 256
#define DD 64
#define KH 2

// ---------------- scratch (static device globals; no allocation) -------------
__device__ float g_HW [KH*NN*DD];   // [k][n][d]
__device__ float g_e1 [KH*NN];
__device__ float g_e2 [KH*NN];
__device__ float g_p1 [KH*NN];      // exp(e1)
__device__ float g_p51[KH*NN];      // exp(0.2 e1)
__device__ float g_p2 [KH*NN];      // exp(e2)
__device__ float g_p52[KH*NN];      // exp(0.2 e2)
__device__ float g_q1 [KH*NN];      // p1 / Z
__device__ float g_q5 [KH*NN];      // p51 / Z
__device__ unsigned g_mask[NN*(NN/32)];  // bitpacked A, row-major [j][i/32]

// ---------------- kernel 1: HW[k][n][d] = sum_f H[n][f] W[k][f][d] ----------
__global__ void k_hw(const float* __restrict__ H, const float* __restrict__ W) {
    __shared__ float Ws[64][128];   // [f-chunk][k*64+d]
    __shared__ float Hs[32][64];    // [row][f-chunk]
    const int tid = threadIdx.x;
    const int tx = tid & 31;        // -> 4 cols (kd)
    const int ty = tid >> 5;        // -> 4 rows (n)
    const int n0 = blockIdx.x * 32;

    float acc[4][4];
#pragma unroll
    for (int a = 0; a < 4; a++)
#pragma unroll
        for (int b = 0; b < 4; b++) acc[a][b] = 0.f;

    for (int fc = 0; fc < FF; fc += 64) {
#pragma unroll
        for (int q = 0; q < 8; q++) {               // W chunk: 64x128 floats
            int idx = q * 256 + tid;                // float4 index
            int kk = idx >> 5, c4 = idx & 31;
            int c = c4 * 4;
            int k = c >> 6, d = c & 63;
            float4 v = *(const float4*)(W + k * (FF * DD) + (fc + kk) * DD + d);
            *(float4*)(&Ws[kk][c]) = v;
        }
#pragma unroll
        for (int q = 0; q < 2; q++) {               // H tile: 32x64 floats
            int idx = q * 256 + tid;
            int r = idx >> 4, k4 = idx & 15;
            float4 v = *(const float4*)(H + (n0 + r) * FF + fc + k4 * 4);
            *(float4*)(&Hs[r][k4 * 4]) = v;
        }
        __syncthreads();
#pragma unroll 8
        for (int kk = 0; kk < 64; kk++) {
            float4 bv = *(const float4*)(&Ws[kk][tx * 4]);
            float a0 = Hs[ty * 4 + 0][kk];
            float a1 = Hs[ty * 4 + 1][kk];
            float a2 = Hs[ty * 4 + 2][kk];
            float a3 = Hs[ty * 4 + 3][kk];
            acc[0][0] += a0 * bv.x; acc[0][1] += a0 * bv.y; acc[0][2] += a0 * bv.z; acc[0][3] += a0 * bv.w;
            acc[1][0] += a1 * bv.x; acc[1][1] += a1 * bv.y; acc[1][2] += a1 * bv.z; acc[1][3] += a1 * bv.w;
            acc[2][0] += a2 * bv.x; acc[2][1] += a2 * bv.y; acc[2][2] += a2 * bv.z; acc[2][3] += a2 * bv.w;
            acc[3][0] += a3 * bv.x; acc[3][1] += a3 * bv.y; acc[3][2] += a3 * bv.z; acc[3][3] += a3 * bv.w;
        }
        __syncthreads();
    }
    const int c = tx * 4;
    const int k = c >> 6, d = c & 63;
#pragma unroll
    for (int s = 0; s < 4; s++) {
        int n = n0 + ty * 4 + s;
        float4 o = make_float4(acc[s][0], acc[s][1], acc[s][2], acc[s][3]);
        *(float4*)(g_HW + (k * NN + n) * DD + d) = o;
    }
}

// ------- kernel 2: e1/e2 per (k,n) + exp tables --------------------------
__global__ void k_e(const float* __restrict__ a1, const float* __restrict__ a2) {
    __shared__ float a1s[128], a2s[128];
    const int tid = threadIdx.x;
    if (tid < 128) a1s[tid] = a1[tid];
    else           a2s[tid - 128] = a2[tid - 128];
    __syncthreads();
    const int t = blockIdx.x * 256 + tid;     // t = k*8192 + n
    const int k = t >> 13;
    const float* hw = g_HW + (size_t)t * DD;
    const float* A1 = a1s + k * 64;
    const float* A2 = a2s + k * 64;
    float e1 = 0.f, e2 = 0.f;
#pragma unroll
    for (int d4 = 0; d4 < 16; d4++) {
        float4 h = *(const float4*)(hw + d4 * 4);
        e1 += h.x * A1[d4 * 4 + 0] + h.y * A1[d4 * 4 + 1] + h.z * A1[d4 * 4 + 2] + h.w * A1[d4 * 4 + 3];
        e2 += h.x * A2[d4 * 4 + 0] + h.y * A2[d4 * 4 + 1] + h.z * A2[d4 * 4 + 2] + h.w * A2[d4 * 4 + 3];
    }
    g_e1[t] = e1;             g_e2[t] = e2;
    g_p1[t] = expf(e1);       g_p51[t] = expf(0.2f * e1);
    g_p2[t] = expf(e2);       g_p52[t] = expf(0.2f * e2);
}

// ------- kernel 3: softmax denominators Z + bitpack A --------------------
// CTA = 8 rows (j), 256 threads. One full read of A (268 MB), DRAM-bound.
__global__ void k_z(const int* __restrict__ A) {
    __shared__ float e2s[2][256], p2s[2][256], p52s[2][256];
    __shared__ float red[32][8];
    const int tid = threadIdx.x;
    const int lane = tid & 31, wrp = tid >> 5;
    const int j0 = blockIdx.x * 8;

    float e1r[8][2];
#pragma unroll
    for (int j = 0; j < 8; j++) {
        e1r[j][0] = g_e1[j0 + j];
        e1r[j][1] = g_e1[NN + j0 + j];
    }
    float sums[8][2][2];
#pragma unroll
    for (int j = 0; j < 8; j++)
#pragma unroll
        for (int k = 0; k < 2; k++) { sums[j][k][0] = 0.f; sums[j][k][1] = 0.f; }

    for (int ci = 0; ci < 32; ci++) {
#pragma unroll
        for (int q = 0; q < 6; q++) {             // stage 1536 floats
            int idx = q * 256 + tid;
            int arr = idx / 512, k = (idx >> 8) & 1, el = idx & 255;
            int gi = k * NN + ci * 256 + el;
            if (arr == 0)      e2s [k][el] = g_e2 [gi];
            else if (arr == 1) p2s [k][el] = g_p2 [gi];
            else               p52s[k][el] = g_p52[gi];
        }
        __syncthreads();
        const float e2v0 = e2s[0][tid],  e2v1 = e2s[1][tid];
        const float p2v0 = p2s[0][tid],  p2v1 = p2s[1][tid];
        const float p52v0 = p52s[0][tid], p52v1 = p52s[1][tid];
        const int ibase = ci * 256;
#pragma unroll
        for (int j = 0; j < 8; j++) {
            int a = A[(j0 + j) * NN + ibase + tid];
            unsigned bal = __ballot_sync(0xffffffffu, a != 0);
            if (lane == 0) g_mask[(j0 + j) * (NN / 32) + ci * 8 + wrp] = bal;
            float am = (a != 0) ? 1.0f : 0.0f;
            {
                float s = e1r[j][0] + e2v0;
                bool pos = s >= 0.f;
                sums[j][0][0] += am * (pos ? p2v0 : 0.f);
                sums[j][0][1] += am * (pos ? 0.f : p52v0);
            }
            {
                float s = e1r[j][1] + e2v1;
                bool pos = s >= 0.f;
                sums[j][1][0] += am * (pos ? p2v1 : 0.f);
                sums[j][1][1] += am * (pos ? 0.f : p52v1);
            }
        }
        __syncthreads();
    }
    // reduce 32 partials per thread across the CTA
#pragma unroll
    for (int v = 0; v < 32; v++) {
        int j = v >> 2, k = (v >> 1) & 1, tp = v & 1;
        float val = sums[j][k][tp];
        val += __shfl_down_sync(0xffffffffu, val, 16);
        val += __shfl_down_sync(0xffffffffu, val, 8);
        val += __shfl_down_sync(0xffffffffu, val, 4);
        val += __shfl_down_sync(0xffffffffu, val, 2);
        val += __shfl_down_sync(0xffffffffu, val, 1);
        if (lane == 0) red[v][wrp] = val;
    }
    __syncthreads();
    if (tid < 16) {
        int j = tid >> 1, k = tid & 1;
        float s0 = 0.f, s5 = 0.f;
#pragma unroll
        for (int w = 0; w < 8; w++) {
            s0 += red[(j * 2 + k) * 2 + 0][w];
            s5 += red[(j * 2 + k) * 2 + 1][w];
        }
        int gi = k * NN + j0 + j;
        float p1 = g_p1[gi], p51 = g_p51[gi];
        float rZ = 1.0f / (p1 * s0 + p51 * s5);
        g_q1[gi] = p1 * rZ;
        g_q5[gi] = p51 * rZ;
    }
}

// ------- kernel 4: out[k,i,:] = sum_j attn[k,j,i] * HW[k,j,:]  (+b, relu) --
// CTA: one head, 64 output rows (i), all 64 d. Fused flash-style: build the
// 64x64 attn tile in smem from exp tables + mask bits, then 4x4 SIMT FFMA.
__global__ void k_out(const float* __restrict__ b, float* __restrict__ out) {
    __shared__ float wsm[64][64];       // attn tile [j][i]
    __shared__ float gsm[64][64];       // HW tile   [j][d]
    __shared__ float e1t[64], q1t[64], q5t[64];
    __shared__ float e2t[64], p2t[64], p52t[64];
    __shared__ unsigned maskt[64][2];

    const int tid = threadIdx.x;
    const int k = blockIdx.y;
    const int i0 = blockIdx.x * 64;
    const int tx = tid & 15;            // i-group (4 rows)
    const int tyd = tid >> 4;           // d-group (4 cols)
    const int kb = k * NN;

    if (tid < 64)        e2t [tid]       = g_e2 [kb + i0 + tid];
    else if (tid < 128)  p2t [tid - 64]  = g_p2 [kb + i0 + tid - 64];
    else if (tid < 192)  p52t[tid - 128] = g_p52[kb + i0 + tid - 128];
    __syncthreads();

    const int iw = tid & 63;            // this thread's fixed i within tile (for w-build)
    const int jb = tid >> 6;            // 0..3
    const float e2v = e2t[iw], p2v = p2t[iw], p52v = p52t[iw];
    const int widx = iw >> 5, shft = iw & 31;
    const int w0 = i0 >> 5;             // mask word base

    float acc[4][4];
#pragma unroll
    for (int a = 0; a < 4; a++)
#pragma unroll
        for (int c = 0; c < 4; c++) acc[a][c] = 0.f;

    for (int jt = 0; jt < NN / 64; jt++) {
        const int j0 = jt * 64;
        __syncthreads();                               // prev MMA done with smem
#pragma unroll
        for (int q = 0; q < 4; q++) {                  // stage HW tile
            int idx = q * 256 + tid;
            int j = idx >> 4, d4 = idx & 15;
            *(float4*)(&gsm[j][d4 * 4]) =
                *(const float4*)(g_HW + (size_t)(kb + j0 + j) * DD + d4 * 4);
        }
        if (tid < 64)       e1t[tid]       = g_e1[kb + j0 + tid];
        else if (tid < 128) q1t[tid - 64]  = g_q1[kb + j0 + tid - 64];
        else if (tid < 192) q5t[tid - 128] = g_q5[kb + j0 + tid - 128];
        else {
            int t2 = tid - 192;                        // 0..63
            maskt[t2][0] = g_mask[(j0 + t2) * (NN / 32) + w0];
            maskt[t2][1] = g_mask[(j0 + t2) * (NN / 32) + w0 + 1];
        }
        __syncthreads();
        // build attn tile: each thread does 16 j's at its fixed i
#pragma unroll
        for (int q = 0; q < 16; q++) {
            int j = q * 4 + jb;
            float s = e1t[j] + e2v;
            bool pos = s >= 0.f;
            unsigned bit = (maskt[j][widx] >> shft) & 1u;
            float w = bit ? ((pos ? q1t[j] : q5t[j]) * (pos ? p2v : p52v)) : 0.f;
            wsm[j][iw] = w;
        }
        __syncthreads();
#pragma unroll 8
        for (int j = 0; j < 64; j++) {
            float4 wv = *(const float4*)(&wsm[j][tx * 4]);
            float4 gv = *(const float4*)(&gsm[j][tyd * 4]);
            acc[0][0] += wv.x * gv.x; acc[0][1] += wv.x * gv.y; acc[0][2] += wv.x * gv.z; acc[0][3] += wv.x * gv.w;
            acc[1][0] += wv.y * gv.x; acc[1][1] += wv.y * gv.y; acc[1][2] += wv.y * gv.z; acc[1][3] += wv.y * gv.w;
            acc[2][0] += wv.z * gv.x; acc[2][1] += wv.z * gv.y; acc[2][2] += wv.z * gv.z; acc[2][3] += wv.z * gv.w;
            acc[3][0] += wv.w * gv.x; acc[3][1] += wv.w * gv.y; acc[3][2] += wv.w * gv.z; acc[3][3] += wv.w * gv.w;
        }
    }
    float4 bv = *(const float4*)(b + k * 64 + tyd * 4);
#pragma unroll
    for (int si = 0; si < 4; si++) {
        int row = i0 + tx * 4 + si;
        float4 o;
        o.x = fmaxf(acc[si][0] + bv.x, 0.f);
        o.y = fmaxf(acc[si][1] + bv.y, 0.f);
        o.z = fmaxf(acc[si][2] + bv.z, 0.f);
        o.w = fmaxf(acc[si][3] + bv.w, 0.f);
        *(float4*)(out + (size_t)row * (KH * DD) + k * 64 + tyd * 4) = o;
    }
}

// ---------------------------------------------------------------------------
extern "C" void kernel_launch(void* const* d_in, const int* in_sizes, int n_in,
                              void* d_out, int out_size) {
    const float* H  = (const float*)d_in[0];   // [8192,256]
    const int*   A  = (const int*)  d_in[1];   // [8192,8192]
    const float* W  = (const float*)d_in[2];   // [2,256,64]
    const float* b  = (const float*)d_in[3];   // [2,64]
    const float* a1 = (const float*)d_in[4];   // [2,64]
    const float* a2 = (const float*)d_in[5];   // [2,64]
    float* out = (float*)d_out;                // [8192,128]

    k_hw <<<NN / 32, 256>>>(H, W);
    k_e  <<<(KH * NN) / 256, 256>>>(a1, a2);
    k_z  <<<NN / 8, 256>>>(A);
    k_out<<<dim3(NN / 64, KH), 256>>>(b, out);
}